// round 11
// baseline (speedup 1.0000x reference)
#include <cuda_runtime.h>
#include <math.h>

// Problem constants
#define NB 16
#define NC 3
#define NT 600
#define HW 5184          // 72*72
#define HW4 (HW/4)       // 1296 float4 per row
#define ROWS (NB*NC*NT)  // 28800
#define ROWS_PER_B (NC*NT)  // 1800

// Scratch: spatial means [b][c][t]; per-batch completion counters.
// g_cnt is zero-initialized at load; each finisher resets its counter,
// so every graph replay starts from zero.
__device__ float g_x[ROWS];
__device__ unsigned int g_cnt[NB];

// ---------------------------------------------------------------------------
// Single fused kernel. One block per (b,c,t) row:
//   1) stream 20.7 KB row, reduce to spatial mean, store to g_x
//   2) release-fence + atomicAdd per-batch counter
//   3) the LAST block of each batch becomes the finisher: Gram reduce over
//      the 1800 L2-hot means, thread-0 all-float eigensolve, projection,
//      counter reset. 15/16 finishers hide under remaining streaming.
// ---------------------------------------------------------------------------
__global__ __launch_bounds__(256) void lgi_fused_kernel(const float* __restrict__ in,
                                                        float* __restrict__ out) {
    const int row = blockIdx.x;
    const int b = row / ROWS_PER_B;
    const float4* p = reinterpret_cast<const float4*>(in) + (size_t)row * HW4;

    // ---- Phase 1: row mean (pure HBM streaming) ----
    float s0 = 0.0f, s1 = 0.0f;
    int i = threadIdx.x;
    for (; i + 256 < HW4; i += 512) {
        float4 v0 = __ldg(&p[i]);
        float4 v1 = __ldg(&p[i + 256]);
        s0 += (v0.x + v0.y) + (v0.z + v0.w);
        s1 += (v1.x + v1.y) + (v1.z + v1.w);
    }
    if (i < HW4) {
        float4 v = __ldg(&p[i]);
        s0 += (v.x + v.y) + (v.z + v.w);
    }
    float s = s0 + s1;

    #pragma unroll
    for (int o = 16; o > 0; o >>= 1) s += __shfl_down_sync(0xffffffffu, s, o);

    __shared__ float ws[8];
    __shared__ bool is_last;
    const int lane = threadIdx.x & 31;
    const int warp = threadIdx.x >> 5;
    if (lane == 0) ws[warp] = s;
    __syncthreads();

    if (threadIdx.x == 0) {
        float m = 0.0f;
        #pragma unroll
        for (int w = 0; w < 8; ++w) m += ws[w];
        g_x[row] = m * (1.0f / (float)HW);
        __threadfence();                       // release: mean visible before count
        unsigned int c = atomicAdd(&g_cnt[b], 1u);
        is_last = (c == ROWS_PER_B - 1);
    }
    __syncthreads();
    if (!is_last) return;

    // ---- Phase 2 (finisher block only): acquire, Gram, solve, project ----
    __threadfence();                           // acquire: see all 1800 means

    const float* x0 = g_x + (size_t)b * ROWS_PER_B;
    const float* x1 = x0 + NT;
    const float* x2 = x0 + 2 * NT;

    __shared__ float gm[6];
    __shared__ float sv[3];
    if (threadIdx.x < 6) gm[threadIdx.x] = 0.0f;
    __syncthreads();

    float m00 = 0, m01 = 0, m02 = 0, m11 = 0, m12 = 0, m22 = 0;
    for (int n = threadIdx.x; n < NT; n += 256) {
        float a = x0[n], c = x1[n], d = x2[n];
        m00 = fmaf(a, a, m00); m01 = fmaf(a, c, m01); m02 = fmaf(a, d, m02);
        m11 = fmaf(c, c, m11); m12 = fmaf(c, d, m12); m22 = fmaf(d, d, m22);
    }
    #pragma unroll
    for (int o = 16; o > 0; o >>= 1) {
        m00 += __shfl_down_sync(0xffffffffu, m00, o);
        m01 += __shfl_down_sync(0xffffffffu, m01, o);
        m02 += __shfl_down_sync(0xffffffffu, m02, o);
        m11 += __shfl_down_sync(0xffffffffu, m11, o);
        m12 += __shfl_down_sync(0xffffffffu, m12, o);
        m22 += __shfl_down_sync(0xffffffffu, m22, o);
    }
    if (lane == 0) {
        atomicAdd(&gm[0], m00); atomicAdd(&gm[1], m01); atomicAdd(&gm[2], m02);
        atomicAdd(&gm[3], m11); atomicAdd(&gm[4], m12); atomicAdd(&gm[5], m22);
    }
    __syncthreads();

    if (threadIdx.x == 0) {
        const float f00 = gm[0], f01 = gm[1], f02 = gm[2];
        const float f11 = gm[3], f12 = gm[4], f22 = gm[5];

        // Trig dominant eigenvalue (float; __cosf hits MUFU)
        float p1 = f01 * f01 + f02 * f02 + f12 * f12;
        float q = (f00 + f11 + f22) * (1.0f / 3.0f);
        float d0 = f00 - q, d1 = f11 - q, d2 = f22 - q;
        float p2 = d0 * d0 + d1 * d1 + d2 * d2 + 2.0f * p1;
        float pf = sqrtf(p2 * (1.0f / 6.0f));
        float lam = q;
        if (pf > 0.0f) {
            float ip = __fdividef(1.0f, pf);
            float b00 = d0 * ip, b11 = d1 * ip, b22 = d2 * ip;
            float b01 = f01 * ip, b02 = f02 * ip, b12 = f12 * ip;
            float detB = b00 * (b11 * b22 - b12 * b12)
                       - b01 * (b01 * b22 - b12 * b02)
                       + b02 * (b01 * b12 - b11 * b02);
            float r = fminf(1.0f, fmaxf(-1.0f, 0.5f * detB));
            lam = q + 2.0f * pf * __cosf(acosf(r) * (1.0f / 3.0f));
        }

        // Two passes: cross-product eigenvector, Rayleigh-refined lambda
        float vx = 0.5773503f, vy = 0.5773503f, vz = 0.5773503f;
        const float trf = f00 + f11 + f22;
        bool ok = false;

        #pragma unroll
        for (int pass = 0; pass < 2; ++pass) {
            float g0x = f00 - lam, g0y = f01,       g0z = f02;
            float g1x = f01,       g1y = f11 - lam, g1z = f12;
            float g2x = f02,       g2y = f12,       g2z = f22 - lam;

            float e0x = g0y * g1z - g0z * g1y, e0y = g0z * g1x - g0x * g1z, e0z = g0x * g1y - g0y * g1x;
            float e1x = g1y * g2z - g1z * g2y, e1y = g1z * g2x - g1x * g2z, e1z = g1x * g2y - g1y * g2x;
            float e2x = g2y * g0z - g2z * g0y, e2y = g2z * g0x - g2x * g0z, e2z = g2x * g0y - g2y * g0x;

            float q0 = e0x * e0x + e0y * e0y + e0z * e0z;
            float q1 = e1x * e1x + e1y * e1y + e1z * e1z;
            float q2 = e2x * e2x + e2y * e2y + e2z * e2z;

            float wx, wy, wz, nn;
            if (q0 >= q1 && q0 >= q2) { wx = e0x; wy = e0y; wz = e0z; nn = q0; }
            else if (q1 >= q2)        { wx = e1x; wy = e1y; wz = e1z; nn = q1; }
            else                      { wx = e2x; wy = e2y; wz = e2z; nn = q2; }

            if (!(nn > 1e-16f * trf * trf * trf * trf)) break;
            ok = true;

            float inv = rsqrtf(nn);
            vx = wx * inv; vy = wy * inv; vz = wz * inv;

            if (pass == 0) {
                float tx = f00 * vx + f01 * vy + f02 * vz;
                float ty = f01 * vx + f11 * vy + f12 * vz;
                float tz = f02 * vx + f12 * vy + f22 * vz;
                lam = vx * tx + vy * ty + vz * tz;
            }
        }

        if (!ok) {
            // Degenerate fallback: float power iteration (rare path)
            vx = 0.5773503f; vy = 0.5773503f; vz = 0.5773503f;
            for (int it = 0; it < 48; ++it) {
                float tx = f00 * vx + f01 * vy + f02 * vz;
                float ty = f01 * vx + f11 * vy + f12 * vz;
                float tz = f02 * vx + f12 * vy + f22 * vz;
                float inv = rsqrtf(tx * tx + ty * ty + tz * tz + 1e-30f);
                vx = tx * inv; vy = ty * inv; vz = tz * inv;
            }
        }
        sv[0] = vx; sv[1] = vy; sv[2] = vz;

        g_cnt[b] = 0u;   // reset for next graph replay
        __threadfence(); // make reset globally visible before kernel end
    }
    __syncthreads();

    const float t0 = sv[0], t1 = sv[1], t2 = sv[2];
    for (int n = threadIdx.x; n < NT; n += 256) {
        float a = x0[n], c = x1[n], d = x2[n];
        float dot = t0 * a + t1 * c + t2 * d;
        out[(size_t)b * NT + n] = c - t1 * dot;
    }
}

extern "C" void kernel_launch(void* const* d_in, const int* in_sizes, int n_in,
                              void* d_out, int out_size) {
    const float* batch_x = (const float*)d_in[0];
    float* out = (float*)d_out;

    lgi_fused_kernel<<<ROWS, 256>>>(batch_x, out);
}

// round 12
// speedup vs baseline: 1.1417x; 1.1417x over previous
#include <cuda_runtime.h>
#include <math.h>

// Problem constants
#define NB 16
#define NC 3
#define NT 600
#define HW 5184          // 72*72
#define HW4 (HW/4)       // 1296 float4 per row
#define ROWS (NB*NC*NT)  // 28800

// Scratch: spatial means, layout [b][c][t]
__device__ float g_x[ROWS];

// ---------------------------------------------------------------------------
// Kernel 1: TWO adjacent rows per block (grid = ROWS/2). Interleaved loads
// give 4 independent load streams per iteration (MLP ~4/thread), ~10 loads
// per thread lifetime. Two warp-reduces at the end, one mean store each.
// ---------------------------------------------------------------------------
__global__ __launch_bounds__(256) void mean_kernel(const float* __restrict__ in,
                                                   float* __restrict__ xout) {
    const int pr = blockIdx.x;               // row pair index
    const int row0 = pr * 2;
    const float4* p0 = reinterpret_cast<const float4*>(in) + (size_t)row0 * HW4;
    const float4* p1 = p0 + HW4;             // adjacent row, contiguous

    float a0 = 0.0f, a1 = 0.0f, b0 = 0.0f, b1 = 0.0f;
    int i = threadIdx.x;
    for (; i + 256 < HW4; i += 512) {
        float4 u0 = __ldg(&p0[i]);
        float4 u1 = __ldg(&p0[i + 256]);
        float4 w0 = __ldg(&p1[i]);
        float4 w1 = __ldg(&p1[i + 256]);
        a0 += (u0.x + u0.y) + (u0.z + u0.w);
        a1 += (u1.x + u1.y) + (u1.z + u1.w);
        b0 += (w0.x + w0.y) + (w0.z + w0.w);
        b1 += (w1.x + w1.y) + (w1.z + w1.w);
    }
    if (i < HW4) {
        float4 u = __ldg(&p0[i]);
        float4 w = __ldg(&p1[i]);
        a0 += (u.x + u.y) + (u.z + u.w);
        b0 += (w.x + w.y) + (w.z + w.w);
    }
    float sa = a0 + a1;
    float sb = b0 + b1;

    #pragma unroll
    for (int o = 16; o > 0; o >>= 1) {
        sa += __shfl_down_sync(0xffffffffu, sa, o);
        sb += __shfl_down_sync(0xffffffffu, sb, o);
    }

    __shared__ float wsa[8], wsb[8];
    const int lane = threadIdx.x & 31;
    const int warp = threadIdx.x >> 5;
    if (lane == 0) { wsa[warp] = sa; wsb[warp] = sb; }
    __syncthreads();
    if (threadIdx.x == 0) {
        float ma = 0.0f, mb = 0.0f;
        #pragma unroll
        for (int w = 0; w < 8; ++w) { ma += wsa[w]; mb += wsb[w]; }
        xout[row0]     = ma * (1.0f / (float)HW);
        xout[row0 + 1] = mb * (1.0f / (float)HW);
    }
}

// ---------------------------------------------------------------------------
// Kernel 2: per batch — float Gram reduce, thread-0 ALL-FLOAT eigensolve
// (trig + cross-product + one Rayleigh refinement pass; no fp64),
// projection. One block per batch element. (Proven: 6.2us, rel_err 4e-6.)
// ---------------------------------------------------------------------------
__global__ __launch_bounds__(256) void project_kernel(const float* __restrict__ x,
                                                      float* __restrict__ out) {
    const int b = blockIdx.x;
    const float* x0 = x + (size_t)b * NC * NT;
    const float* x1 = x0 + NT;
    const float* x2 = x0 + 2 * NT;

    __shared__ float gm[6];
    __shared__ float sv[3];
    if (threadIdx.x < 6) gm[threadIdx.x] = 0.0f;
    __syncthreads();

    float m00 = 0, m01 = 0, m02 = 0, m11 = 0, m12 = 0, m22 = 0;
    for (int n = threadIdx.x; n < NT; n += blockDim.x) {
        float a = x0[n], c = x1[n], d = x2[n];
        m00 = fmaf(a, a, m00); m01 = fmaf(a, c, m01); m02 = fmaf(a, d, m02);
        m11 = fmaf(c, c, m11); m12 = fmaf(c, d, m12); m22 = fmaf(d, d, m22);
    }
    #pragma unroll
    for (int o = 16; o > 0; o >>= 1) {
        m00 += __shfl_down_sync(0xffffffffu, m00, o);
        m01 += __shfl_down_sync(0xffffffffu, m01, o);
        m02 += __shfl_down_sync(0xffffffffu, m02, o);
        m11 += __shfl_down_sync(0xffffffffu, m11, o);
        m12 += __shfl_down_sync(0xffffffffu, m12, o);
        m22 += __shfl_down_sync(0xffffffffu, m22, o);
    }
    if ((threadIdx.x & 31) == 0) {
        atomicAdd(&gm[0], m00); atomicAdd(&gm[1], m01); atomicAdd(&gm[2], m02);
        atomicAdd(&gm[3], m11); atomicAdd(&gm[4], m12); atomicAdd(&gm[5], m22);
    }
    __syncthreads();

    if (threadIdx.x == 0) {
        const float f00 = gm[0], f01 = gm[1], f02 = gm[2];
        const float f11 = gm[3], f12 = gm[4], f22 = gm[5];

        // Trig dominant eigenvalue (float; __cosf hits MUFU)
        float p1 = f01 * f01 + f02 * f02 + f12 * f12;
        float q = (f00 + f11 + f22) * (1.0f / 3.0f);
        float d0 = f00 - q, d1 = f11 - q, d2 = f22 - q;
        float p2 = d0 * d0 + d1 * d1 + d2 * d2 + 2.0f * p1;
        float pf = sqrtf(p2 * (1.0f / 6.0f));
        float lam = q;
        if (pf > 0.0f) {
            float ip = __fdividef(1.0f, pf);
            float b00 = d0 * ip, b11 = d1 * ip, b22 = d2 * ip;
            float b01 = f01 * ip, b02 = f02 * ip, b12 = f12 * ip;
            float detB = b00 * (b11 * b22 - b12 * b12)
                       - b01 * (b01 * b22 - b12 * b02)
                       + b02 * (b01 * b12 - b11 * b02);
            float r = fminf(1.0f, fmaxf(-1.0f, 0.5f * detB));
            lam = q + 2.0f * pf * __cosf(acosf(r) * (1.0f / 3.0f));
        }

        // Two passes: cross-product eigenvector, Rayleigh-refined lambda
        float vx = 0.5773503f, vy = 0.5773503f, vz = 0.5773503f;
        const float trf = f00 + f11 + f22;
        bool ok = false;

        #pragma unroll
        for (int pass = 0; pass < 2; ++pass) {
            float g0x = f00 - lam, g0y = f01,       g0z = f02;
            float g1x = f01,       g1y = f11 - lam, g1z = f12;
            float g2x = f02,       g2y = f12,       g2z = f22 - lam;

            float e0x = g0y * g1z - g0z * g1y, e0y = g0z * g1x - g0x * g1z, e0z = g0x * g1y - g0y * g1x;
            float e1x = g1y * g2z - g1z * g2y, e1y = g1z * g2x - g1x * g2z, e1z = g1x * g2y - g1y * g2x;
            float e2x = g2y * g0z - g2z * g0y, e2y = g2z * g0x - g2x * g0z, e2z = g2x * g0y - g2y * g0x;

            float q0 = e0x * e0x + e0y * e0y + e0z * e0z;
            float q1 = e1x * e1x + e1y * e1y + e1z * e1z;
            float q2 = e2x * e2x + e2y * e2y + e2z * e2z;

            float wx, wy, wz, nn;
            if (q0 >= q1 && q0 >= q2) { wx = e0x; wy = e0y; wz = e0z; nn = q0; }
            else if (q1 >= q2)        { wx = e1x; wy = e1y; wz = e1z; nn = q1; }
            else                      { wx = e2x; wy = e2y; wz = e2z; nn = q2; }

            if (!(nn > 1e-16f * trf * trf * trf * trf)) break;
            ok = true;

            float inv = rsqrtf(nn);
            vx = wx * inv; vy = wy * inv; vz = wz * inv;

            if (pass == 0) {
                float tx = f00 * vx + f01 * vy + f02 * vz;
                float ty = f01 * vx + f11 * vy + f12 * vz;
                float tz = f02 * vx + f12 * vy + f22 * vz;
                lam = vx * tx + vy * ty + vz * tz;
            }
        }

        if (!ok) {
            // Degenerate fallback: float power iteration (rare path)
            vx = 0.5773503f; vy = 0.5773503f; vz = 0.5773503f;
            for (int it = 0; it < 48; ++it) {
                float tx = f00 * vx + f01 * vy + f02 * vz;
                float ty = f01 * vx + f11 * vy + f12 * vz;
                float tz = f02 * vx + f12 * vy + f22 * vz;
                float inv = rsqrtf(tx * tx + ty * ty + tz * tz + 1e-30f);
                vx = tx * inv; vy = ty * inv; vz = tz * inv;
            }
        }
        sv[0] = vx; sv[1] = vy; sv[2] = vz;
    }
    __syncthreads();

    const float s0 = sv[0], s1 = sv[1], s2 = sv[2];
    for (int n = threadIdx.x; n < NT; n += blockDim.x) {
        float a = x0[n], c = x1[n], d = x2[n];
        float dot = s0 * a + s1 * c + s2 * d;
        out[(size_t)b * NT + n] = c - s1 * dot;
    }
}

extern "C" void kernel_launch(void* const* d_in, const int* in_sizes, int n_in,
                              void* d_out, int out_size) {
    const float* batch_x = (const float*)d_in[0];
    float* out = (float*)d_out;

    float* xbuf;
    cudaGetSymbolAddress((void**)&xbuf, g_x);

    mean_kernel<<<ROWS / 2, 256>>>(batch_x, xbuf);
    project_kernel<<<NB, 256>>>(xbuf, out);
}

// round 14
// speedup vs baseline: 1.1574x; 1.0137x over previous
#include <cuda_runtime.h>
#include <math.h>

// Problem constants
#define NB 16
#define NC 3
#define NT 600
#define HW 5184          // 72*72
#define HW4 (HW/4)       // 1296 float4 per row
#define ROWS (NB*NC*NT)  // 28800

// Scratch: spatial means, layout [b][c][t]
__device__ float g_x[ROWS];

// ---------------------------------------------------------------------------
// Kernel 1: FOUR adjacent rows per block (grid = ROWS/4). Four independent
// load streams per iteration (sustained MLP~4/thread), 4x block lifetime
// (fewer wave transitions), streaming loads (__ldcs: read-once data, keep
// it out of L2 retention).
// ---------------------------------------------------------------------------
__global__ __launch_bounds__(256) void mean_kernel(const float* __restrict__ in,
                                                   float* __restrict__ xout) {
    const int row0 = blockIdx.x * 4;
    const float4* p0 = reinterpret_cast<const float4*>(in) + (size_t)row0 * HW4;
    const float4* p1 = p0 + HW4;
    const float4* p2 = p0 + 2 * HW4;
    const float4* p3 = p0 + 3 * HW4;

    float sa = 0.0f, sb = 0.0f, sc = 0.0f, sd = 0.0f;
    for (int i = threadIdx.x; i < HW4; i += 256) {
        float4 u0 = __ldcs(&p0[i]);
        float4 u1 = __ldcs(&p1[i]);
        float4 u2 = __ldcs(&p2[i]);
        float4 u3 = __ldcs(&p3[i]);
        sa += (u0.x + u0.y) + (u0.z + u0.w);
        sb += (u1.x + u1.y) + (u1.z + u1.w);
        sc += (u2.x + u2.y) + (u2.z + u2.w);
        sd += (u3.x + u3.y) + (u3.z + u3.w);
    }

    #pragma unroll
    for (int o = 16; o > 0; o >>= 1) {
        sa += __shfl_down_sync(0xffffffffu, sa, o);
        sb += __shfl_down_sync(0xffffffffu, sb, o);
        sc += __shfl_down_sync(0xffffffffu, sc, o);
        sd += __shfl_down_sync(0xffffffffu, sd, o);
    }

    __shared__ float ws[8][4];
    const int lane = threadIdx.x & 31;
    const int warp = threadIdx.x >> 5;
    if (lane == 0) { ws[warp][0] = sa; ws[warp][1] = sb; ws[warp][2] = sc; ws[warp][3] = sd; }
    __syncthreads();
    if (threadIdx.x < 4) {
        float m = 0.0f;
        #pragma unroll
        for (int w = 0; w < 8; ++w) m += ws[w][threadIdx.x];
        xout[row0 + threadIdx.x] = m * (1.0f / (float)HW);
    }
}

// ---------------------------------------------------------------------------
// Kernel 2: per batch — float Gram reduce, thread-0 ALL-FLOAT eigensolve
// (trig + cross-product + one Rayleigh refinement pass; no fp64),
// projection. One block per batch element. (Proven: 6.3us, rel_err 4e-6.)
// ---------------------------------------------------------------------------
__global__ __launch_bounds__(256) void project_kernel(const float* __restrict__ x,
                                                      float* __restrict__ out) {
    const int b = blockIdx.x;
    const float* x0 = x + (size_t)b * NC * NT;
    const float* x1 = x0 + NT;
    const float* x2 = x0 + 2 * NT;

    __shared__ float gm[6];
    __shared__ float sv[3];
    if (threadIdx.x < 6) gm[threadIdx.x] = 0.0f;
    __syncthreads();

    float m00 = 0, m01 = 0, m02 = 0, m11 = 0, m12 = 0, m22 = 0;
    for (int n = threadIdx.x; n < NT; n += blockDim.x) {
        float a = x0[n], c = x1[n], d = x2[n];
        m00 = fmaf(a, a, m00); m01 = fmaf(a, c, m01); m02 = fmaf(a, d, m02);
        m11 = fmaf(c, c, m11); m12 = fmaf(c, d, m12); m22 = fmaf(d, d, m22);
    }
    #pragma unroll
    for (int o = 16; o > 0; o >>= 1) {
        m00 += __shfl_down_sync(0xffffffffu, m00, o);
        m01 += __shfl_down_sync(0xffffffffu, m01, o);
        m02 += __shfl_down_sync(0xffffffffu, m02, o);
        m11 += __shfl_down_sync(0xffffffffu, m11, o);
        m12 += __shfl_down_sync(0xffffffffu, m12, o);
        m22 += __shfl_down_sync(0xffffffffu, m22, o);
    }
    if ((threadIdx.x & 31) == 0) {
        atomicAdd(&gm[0], m00); atomicAdd(&gm[1], m01); atomicAdd(&gm[2], m02);
        atomicAdd(&gm[3], m11); atomicAdd(&gm[4], m12); atomicAdd(&gm[5], m22);
    }
    __syncthreads();

    if (threadIdx.x == 0) {
        const float f00 = gm[0], f01 = gm[1], f02 = gm[2];
        const float f11 = gm[3], f12 = gm[4], f22 = gm[5];

        // Trig dominant eigenvalue (float; __cosf hits MUFU)
        float p1 = f01 * f01 + f02 * f02 + f12 * f12;
        float q = (f00 + f11 + f22) * (1.0f / 3.0f);
        float d0 = f00 - q, d1 = f11 - q, d2 = f22 - q;
        float p2 = d0 * d0 + d1 * d1 + d2 * d2 + 2.0f * p1;
        float pf = sqrtf(p2 * (1.0f / 6.0f));
        float lam = q;
        if (pf > 0.0f) {
            float ip = __fdividef(1.0f, pf);
            float b00 = d0 * ip, b11 = d1 * ip, b22 = d2 * ip;
            float b01 = f01 * ip, b02 = f02 * ip, b12 = f12 * ip;
            float detB = b00 * (b11 * b22 - b12 * b12)
                       - b01 * (b01 * b22 - b12 * b02)
                       + b02 * (b01 * b12 - b11 * b02);
            float r = fminf(1.0f, fmaxf(-1.0f, 0.5f * detB));
            lam = q + 2.0f * pf * __cosf(acosf(r) * (1.0f / 3.0f));
        }

        // Two passes: cross-product eigenvector, Rayleigh-refined lambda
        float vx = 0.5773503f, vy = 0.5773503f, vz = 0.5773503f;
        const float trf = f00 + f11 + f22;
        bool ok = false;

        #pragma unroll
        for (int pass = 0; pass < 2; ++pass) {
            float g0x = f00 - lam, g0y = f01,       g0z = f02;
            float g1x = f01,       g1y = f11 - lam, g1z = f12;
            float g2x = f02,       g2y = f12,       g2z = f22 - lam;

            float e0x = g0y * g1z - g0z * g1y, e0y = g0z * g1x - g0x * g1z, e0z = g0x * g1y - g0y * g1x;
            float e1x = g1y * g2z - g1z * g2y, e1y = g1z * g2x - g1x * g2z, e1z = g1x * g2y - g1y * g2x;
            float e2x = g2y * g0z - g2z * g0y, e2y = g2z * g0x - g2x * g0z, e2z = g2x * g0y - g2y * g0x;

            float q0 = e0x * e0x + e0y * e0y + e0z * e0z;
            float q1 = e1x * e1x + e1y * e1y + e1z * e1z;
            float q2 = e2x * e2x + e2y * e2y + e2z * e2z;

            float wx, wy, wz, nn;
            if (q0 >= q1 && q0 >= q2) { wx = e0x; wy = e0y; wz = e0z; nn = q0; }
            else if (q1 >= q2)        { wx = e1x; wy = e1y; wz = e1z; nn = q1; }
            else                      { wx = e2x; wy = e2y; wz = e2z; nn = q2; }

            if (!(nn > 1e-16f * trf * trf * trf * trf)) break;
            ok = true;

            float inv = rsqrtf(nn);
            vx = wx * inv; vy = wy * inv; vz = wz * inv;

            if (pass == 0) {
                float tx = f00 * vx + f01 * vy + f02 * vz;
                float ty = f01 * vx + f11 * vy + f12 * vz;
                float tz = f02 * vx + f12 * vy + f22 * vz;
                lam = vx * tx + vy * ty + vz * tz;
            }
        }

        if (!ok) {
            // Degenerate fallback: float power iteration (rare path)
            vx = 0.5773503f; vy = 0.5773503f; vz = 0.5773503f;
            for (int it = 0; it < 48; ++it) {
                float tx = f00 * vx + f01 * vy + f02 * vz;
                float ty = f01 * vx + f11 * vy + f12 * vz;
                float tz = f02 * vx + f12 * vy + f22 * vz;
                float inv = rsqrtf(tx * tx + ty * ty + tz * tz + 1e-30f);
                vx = tx * inv; vy = ty * inv; vz = tz * inv;
            }
        }
        sv[0] = vx; sv[1] = vy; sv[2] = vz;
    }
    __syncthreads();

    const float s0 = sv[0], s1 = sv[1], s2 = sv[2];
    for (int n = threadIdx.x; n < NT; n += blockDim.x) {
        float a = x0[n], c = x1[n], d = x2[n];
        float dot = s0 * a + s1 * c + s2 * d;
        out[(size_t)b * NT + n] = c - s1 * dot;
    }
}

extern "C" void kernel_launch(void* const* d_in, const int* in_sizes, int n_in,
                              void* d_out, int out_size) {
    const float* batch_x = (const float*)d_in[0];
    float* out = (float*)d_out;

    float* xbuf;
    cudaGetSymbolAddress((void**)&xbuf, g_x);

    mean_kernel<<<ROWS / 4, 256>>>(batch_x, xbuf);
    project_kernel<<<NB, 256>>>(xbuf, out);
}

// round 17
// speedup vs baseline: 1.1656x; 1.0071x over previous
#include <cuda_runtime.h>
#include <math.h>

// Problem constants
#define NB 16
#define NC 3
#define NT 600
#define HW 5184          // 72*72
#define HW4 (HW/4)       // 1296 float4 per row
#define ROWS (NB*NC*NT)  // 28800

// Scratch: spatial means, layout [b][c][t]
__device__ float g_x[ROWS];

// ---------------------------------------------------------------------------
// Kernel 1: FOUR adjacent rows per block (grid = ROWS/4). Four independent
// load streams per iteration, streaming loads (__ldcs). Fires the PDL
// launch-completion trigger right after its stores so the dependent kernel's
// prologue overlaps with the streaming tail.
// ---------------------------------------------------------------------------
__global__ __launch_bounds__(256) void mean_kernel(const float* __restrict__ in,
                                                   float* __restrict__ xout) {
    const int row0 = blockIdx.x * 4;
    const float4* p0 = reinterpret_cast<const float4*>(in) + (size_t)row0 * HW4;
    const float4* p1 = p0 + HW4;
    const float4* p2 = p0 + 2 * HW4;
    const float4* p3 = p0 + 3 * HW4;

    float sa = 0.0f, sb = 0.0f, sc = 0.0f, sd = 0.0f;
    for (int i = threadIdx.x; i < HW4; i += 256) {
        float4 u0 = __ldcs(&p0[i]);
        float4 u1 = __ldcs(&p1[i]);
        float4 u2 = __ldcs(&p2[i]);
        float4 u3 = __ldcs(&p3[i]);
        sa += (u0.x + u0.y) + (u0.z + u0.w);
        sb += (u1.x + u1.y) + (u1.z + u1.w);
        sc += (u2.x + u2.y) + (u2.z + u2.w);
        sd += (u3.x + u3.y) + (u3.z + u3.w);
    }

    #pragma unroll
    for (int o = 16; o > 0; o >>= 1) {
        sa += __shfl_down_sync(0xffffffffu, sa, o);
        sb += __shfl_down_sync(0xffffffffu, sb, o);
        sc += __shfl_down_sync(0xffffffffu, sc, o);
        sd += __shfl_down_sync(0xffffffffu, sd, o);
    }

    __shared__ float ws[8][4];
    const int lane = threadIdx.x & 31;
    const int warp = threadIdx.x >> 5;
    if (lane == 0) { ws[warp][0] = sa; ws[warp][1] = sb; ws[warp][2] = sc; ws[warp][3] = sd; }
    __syncthreads();
    if (threadIdx.x < 4) {
        float m = 0.0f;
        #pragma unroll
        for (int w = 0; w < 8; ++w) m += ws[w][threadIdx.x];
        xout[row0 + threadIdx.x] = m * (1.0f / (float)HW);
    }
    // PDL: this block's writes are done; allow the dependent launch to proceed
    // once all blocks have triggered/exited.
    cudaTriggerProgrammaticLaunchCompletion();
}

// ---------------------------------------------------------------------------
// Kernel 2 (PDL secondary): prologue overlaps mean_kernel's tail; blocks at
// cudaGridDependencySynchronize() before reading g_x. Then: float Gram
// reduce, thread-0 all-float eigensolve, projection.
// ---------------------------------------------------------------------------
__global__ __launch_bounds__(256) void project_kernel(const float* __restrict__ x,
                                                      float* __restrict__ out) {
    const int b = blockIdx.x;
    const float* x0 = x + (size_t)b * NC * NT;
    const float* x1 = x0 + NT;
    const float* x2 = x0 + 2 * NT;

    __shared__ float gm[6];
    __shared__ float sv[3];
    if (threadIdx.x < 6) gm[threadIdx.x] = 0.0f;
    __syncthreads();

    // Wait for the primary grid's writes to g_x to be visible.
    cudaGridDependencySynchronize();

    float m00 = 0, m01 = 0, m02 = 0, m11 = 0, m12 = 0, m22 = 0;
    for (int n = threadIdx.x; n < NT; n += blockDim.x) {
        float a = x0[n], c = x1[n], d = x2[n];
        m00 = fmaf(a, a, m00); m01 = fmaf(a, c, m01); m02 = fmaf(a, d, m02);
        m11 = fmaf(c, c, m11); m12 = fmaf(c, d, m12); m22 = fmaf(d, d, m22);
    }
    #pragma unroll
    for (int o = 16; o > 0; o >>= 1) {
        m00 += __shfl_down_sync(0xffffffffu, m00, o);
        m01 += __shfl_down_sync(0xffffffffu, m01, o);
        m02 += __shfl_down_sync(0xffffffffu, m02, o);
        m11 += __shfl_down_sync(0xffffffffu, m11, o);
        m12 += __shfl_down_sync(0xffffffffu, m12, o);
        m22 += __shfl_down_sync(0xffffffffu, m22, o);
    }
    if ((threadIdx.x & 31) == 0) {
        atomicAdd(&gm[0], m00); atomicAdd(&gm[1], m01); atomicAdd(&gm[2], m02);
        atomicAdd(&gm[3], m11); atomicAdd(&gm[4], m12); atomicAdd(&gm[5], m22);
    }
    __syncthreads();

    if (threadIdx.x == 0) {
        const float f00 = gm[0], f01 = gm[1], f02 = gm[2];
        const float f11 = gm[3], f12 = gm[4], f22 = gm[5];

        // Trig dominant eigenvalue (float; __cosf hits MUFU)
        float p1 = f01 * f01 + f02 * f02 + f12 * f12;
        float q = (f00 + f11 + f22) * (1.0f / 3.0f);
        float d0 = f00 - q, d1 = f11 - q, d2 = f22 - q;
        float p2 = d0 * d0 + d1 * d1 + d2 * d2 + 2.0f * p1;
        float pf = sqrtf(p2 * (1.0f / 6.0f));
        float lam = q;
        if (pf > 0.0f) {
            float ip = __fdividef(1.0f, pf);
            float b00 = d0 * ip, b11 = d1 * ip, b22 = d2 * ip;
            float b01 = f01 * ip, b02 = f02 * ip, b12 = f12 * ip;
            float detB = b00 * (b11 * b22 - b12 * b12)
                       - b01 * (b01 * b22 - b12 * b02)
                       + b02 * (b01 * b12 - b11 * b02);
            float r = fminf(1.0f, fmaxf(-1.0f, 0.5f * detB));
            lam = q + 2.0f * pf * __cosf(acosf(r) * (1.0f / 3.0f));
        }

        // Two passes: cross-product eigenvector, Rayleigh-refined lambda
        float vx = 0.5773503f, vy = 0.5773503f, vz = 0.5773503f;
        const float trf = f00 + f11 + f22;
        bool ok = false;

        #pragma unroll
        for (int pass = 0; pass < 2; ++pass) {
            float g0x = f00 - lam, g0y = f01,       g0z = f02;
            float g1x = f01,       g1y = f11 - lam, g1z = f12;
            float g2x = f02,       g2y = f12,       g2z = f22 - lam;

            float e0x = g0y * g1z - g0z * g1y, e0y = g0z * g1x - g0x * g1z, e0z = g0x * g1y - g0y * g1x;
            float e1x = g1y * g2z - g1z * g2y, e1y = g1z * g2x - g1x * g2z, e1z = g1x * g2y - g1y * g2x;
            float e2x = g2y * g0z - g2z * g0y, e2y = g2z * g0x - g2x * g0z, e2z = g2x * g0y - g2y * g0x;

            float q0 = e0x * e0x + e0y * e0y + e0z * e0z;
            float q1 = e1x * e1x + e1y * e1y + e1z * e1z;
            float q2 = e2x * e2x + e2y * e2y + e2z * e2z;

            float wx, wy, wz, nn;
            if (q0 >= q1 && q0 >= q2) { wx = e0x; wy = e0y; wz = e0z; nn = q0; }
            else if (q1 >= q2)        { wx = e1x; wy = e1y; wz = e1z; nn = q1; }
            else                      { wx = e2x; wy = e2y; wz = e2z; nn = q2; }

            if (!(nn > 1e-16f * trf * trf * trf * trf)) break;
            ok = true;

            float inv = rsqrtf(nn);
            vx = wx * inv; vy = wy * inv; vz = wz * inv;

            if (pass == 0) {
                float tx = f00 * vx + f01 * vy + f02 * vz;
                float ty = f01 * vx + f11 * vy + f12 * vz;
                float tz = f02 * vx + f12 * vy + f22 * vz;
                lam = vx * tx + vy * ty + vz * tz;
            }
        }

        if (!ok) {
            // Degenerate fallback: float power iteration (rare path)
            vx = 0.5773503f; vy = 0.5773503f; vz = 0.5773503f;
            for (int it = 0; it < 48; ++it) {
                float tx = f00 * vx + f01 * vy + f02 * vz;
                float ty = f01 * vx + f11 * vy + f12 * vz;
                float tz = f02 * vx + f12 * vy + f22 * vz;
                float inv = rsqrtf(tx * tx + ty * ty + tz * tz + 1e-30f);
                vx = tx * inv; vy = ty * inv; vz = tz * inv;
            }
        }
        sv[0] = vx; sv[1] = vy; sv[2] = vz;
    }
    __syncthreads();

    const float s0 = sv[0], s1 = sv[1], s2 = sv[2];
    for (int n = threadIdx.x; n < NT; n += blockDim.x) {
        float a = x0[n], c = x1[n], d = x2[n];
        float dot = s0 * a + s1 * c + s2 * d;
        out[(size_t)b * NT + n] = c - s1 * dot;
    }
}

extern "C" void kernel_launch(void* const* d_in, const int* in_sizes, int n_in,
                              void* d_out, int out_size) {
    const float* batch_x = (const float*)d_in[0];
    float* out = (float*)d_out;

    float* xbuf;
    cudaGetSymbolAddress((void**)&xbuf, g_x);

    mean_kernel<<<ROWS / 4, 256>>>(batch_x, xbuf);

    // PDL secondary launch: prologue overlaps with mean_kernel tail.
    cudaLaunchConfig_t cfg = {};
    cfg.gridDim = dim3(NB, 1, 1);
    cfg.blockDim = dim3(256, 1, 1);
    cfg.dynamicSmemBytes = 0;
    cudaLaunchAttribute attrs[1];
    attrs[0].id = cudaLaunchAttributeProgrammaticStreamSerialization;
    attrs[0].val.programmaticStreamSerializationAllowed = 1;
    cfg.attrs = attrs;
    cfg.numAttrs = 1;
    cudaLaunchKernelEx(&cfg, project_kernel, (const float*)xbuf, out);
}